// round 15
// baseline (speedup 1.0000x reference)
#include <cuda_runtime.h>
#include <cstdint>

// TransitionGNN via legacy mma.sync.m16n8k8 TF32 (single pass).
// R15: TB=128, single 8-warp CTA/SM (4m x 2n, warp tile M32xN64). Halves W/sj
// L2 traffic vs 2x64-row CTAs, and frees smem for TRUE W double-buffering with
// 2-edge lookahead ({sj_{t+1}} and {W_{t+2}} separate cp.async groups).
// B=8192, K=10, D=64, H=128, A=16, E=90, F=208.

#define KN 10
#define TB 128
#define NT 256

// padded row strides (bytes); (stride/4) mod 32 in {4,20} -> ldmatrix conflict-free
#define S_S   272   // states rows: 256B + 16
#define S_A   80    // action rows: 64B + 16
#define S_W   528   // W^T rows: 512B + 16
#define S_WNA 464   // Wn^T chunkA rows: 112*4B + 16
#define S_WNB 400   // Wn^T chunkB rows: 96*4B + 16

// ---- staged scratch (tf32, pre-padded rows) ----
__device__ __align__(16) unsigned char g_s[KN * 8192 * S_S];      // [j][b][64k]
__device__ __align__(16) unsigned char g_a[KN * 8192 * S_A];      // [j][b][16a]
__device__ __align__(16) unsigned char g_We[90 * 128 * S_W];      // W^T [e][128h][128k]
__device__ __align__(16) unsigned char g_WnA[KN * 64 * S_WNA];    // Wn^T [i][64d][f0..111]
__device__ __align__(16) unsigned char g_WnB[KN * 64 * S_WNB];    // Wn^T [i][64d][f112..207]

// ---- smem map (bytes), total 219648 (1 CTA/SM) ----
#define SI    0u                    // 128 x 272 = 34816
#define SJ    34816u                // 34816
#define ACT   69632u                // 128 x 80 = 10240
#define BIAS  79872u                // 4608 (9 x 512)
#define WE0   84480u                // 128 x 528 = 67584 (W ping)
#define WE1   152064u               // 67584 (W pong)
#define SMEM_TOTAL 219648
// node-phase aliases:
#define AGG   (WE0)                 // 128 x 528 = 67584
#define WNA   (WE1)                 // 64 x 464 = 29696
#define WNB   (WE1 + 29696u)        // 64 x 400 = 25600

__device__ __forceinline__ uint32_t tf32c(float x) {
    uint32_t r; asm("cvt.rna.tf32.f32 %0, %1;" : "=r"(r) : "f"(x)); return r;
}
__device__ __forceinline__ float tanha(float x) {
    float r; asm("tanh.approx.f32 %0, %1;" : "=f"(r) : "f"(x)); return r;
}
__device__ __forceinline__ void cp16(uint32_t s, const void* g) {
    asm volatile("cp.async.cg.shared.global [%0], [%1], 16;" :: "r"(s), "l"(g));
}
__device__ __forceinline__ void cpblk(uint32_t sdst, const void* gsrc, int bytes, int tid) {
    for (int off = tid * 16; off < bytes; off += NT * 16)
        cp16(sdst + off, (const char*)gsrc + off);
}
#define CP_COMMIT() asm volatile("cp.async.commit_group;")
#define CP_WAIT(n)  asm volatile("cp.async.wait_group %0;" :: "n"(n))

__device__ __forceinline__ void ldsm4(uint32_t a, uint32_t r[4]) {
    asm volatile("ldmatrix.sync.aligned.m8n8.x4.shared.b16 {%0,%1,%2,%3}, [%4];"
        : "=r"(r[0]), "=r"(r[1]), "=r"(r[2]), "=r"(r[3]) : "r"(a));
}
__device__ __forceinline__ void mma8(float c[4], const uint32_t a[4], uint32_t b0, uint32_t b1) {
    asm volatile("mma.sync.aligned.m16n8k8.row.col.f32.tf32.tf32.f32 "
        "{%0,%1,%2,%3},{%4,%5,%6,%7},{%8,%9},{%0,%1,%2,%3};"
        : "+f"(c[0]), "+f"(c[1]), "+f"(c[2]), "+f"(c[3])
        : "r"(a[0]), "r"(a[1]), "r"(a[2]), "r"(a[3]), "r"(b0), "r"(b1));
}
// A-tile lane base (m16 x k8 x4-ldmatrix); addr(ks) = base + ks*32
__device__ __forceinline__ uint32_t baseA(uint32_t buf, int r0, int S, int lane) {
    int row = r0 + (lane & 7) + ((lane >> 3) & 1) * 8;
    return buf + (uint32_t)(row * S) + ((uint32_t)(lane >> 4) << 4);
}
// B-tile lane base (n16 x k8 x4-ldmatrix from W^T rows=n); addr(ks) = base + ks*32
__device__ __forceinline__ uint32_t baseB(uint32_t buf, int r0, int S, int lane) {
    int row = r0 + (lane & 7) + ((lane >> 4) << 3);
    return buf + (uint32_t)(row * S) + ((uint32_t)((lane >> 3) & 1) << 4);
}

// ===================== prep kernel =====================
__global__ void prep_kernel(const float* __restrict__ states, const float* __restrict__ action,
                            const float* __restrict__ Wed, const float* __restrict__ Wn)
{
    int tid = blockIdx.x * blockDim.x + threadIdx.x;
    int NTH = gridDim.x * blockDim.x;
    for (int p = tid; p < KN * 8192 * 32; p += NTH) {
        int d2 = p & 31, b = (p >> 5) & 8191, j = p >> 18;
        float2 v = *(const float2*)&states[((size_t)b * KN + j) * 64 + 2 * d2];
        uint2 w = { tf32c(v.x), tf32c(v.y) };
        *(uint2*)(g_s + (size_t)(j * 8192 + b) * S_S + d2 * 8) = w;
    }
    for (int p = tid; p < KN * 8192 * 8; p += NTH) {
        int a2 = p & 7, b = (p >> 3) & 8191, j = p >> 16;
        float2 v = *(const float2*)&action[((size_t)b * KN + j) * 16 + 2 * a2];
        uint2 w = { tf32c(v.x), tf32c(v.y) };
        *(uint2*)(g_a + (size_t)(j * 8192 + b) * S_A + a2 * 8) = w;
    }
    for (int p = tid; p < 90 * 128 * 64; p += NTH) {
        int h2 = p & 63, k = (p >> 6) & 127, e = p >> 13;
        float2 v = *(const float2*)&Wed[((size_t)e * 128 + k) * 128 + 2 * h2];
        int h0 = 2 * h2;
        *(uint32_t*)(g_We + (size_t)(e * 128 + h0)     * S_W + k * 4) = tf32c(v.x);
        *(uint32_t*)(g_We + (size_t)(e * 128 + h0 + 1) * S_W + k * 4) = tf32c(v.y);
    }
    for (int p = tid; p < KN * 208 * 32; p += NTH) {
        int d2 = p & 31, fi = p >> 5;
        int f = fi % 208, i = fi / 208;
        float2 v = *(const float2*)&Wn[((size_t)i * 208 + f) * 64 + 2 * d2];
        int d0 = 2 * d2;
        if (f < 112) {
            unsigned char* base = g_WnA + (size_t)i * (64 * S_WNA);
            *(uint32_t*)(base + (size_t)d0       * S_WNA + f * 4) = tf32c(v.x);
            *(uint32_t*)(base + (size_t)(d0 + 1) * S_WNA + f * 4) = tf32c(v.y);
        } else {
            unsigned char* base = g_WnB + (size_t)i * (64 * S_WNB);
            int fc = f - 112;
            *(uint32_t*)(base + (size_t)d0       * S_WNB + fc * 4) = tf32c(v.x);
            *(uint32_t*)(base + (size_t)(d0 + 1) * S_WNB + fc * 4) = tf32c(v.y);
        }
    }
}

// ===================== main kernel =====================
extern "C" __global__ void __launch_bounds__(NT, 1)
gnn_tf32_kernel(const float* __restrict__ b_edge,   // [E,H]
                const float* __restrict__ b_node,   // [K,D]
                float* __restrict__ out)            // [B,K,D]
{
    extern __shared__ char smem[];
    const uint32_t sb = (uint32_t)__cvta_generic_to_shared(smem);

    const int i    = blockIdx.y;
    const int b0   = blockIdx.x * TB;
    const int tid  = threadIdx.x;
    const int lane = tid & 31;
    const int wid  = tid >> 5;
    const int wm   = wid & 3;    // 4 m-warps: rows 32*wm .. +31
    const int wn   = wid >> 2;   // 2 n-warps: edge cols 64*wn, node cols 32*wn
    const int m0   = 32 * wm;

    // ---- prologue: G0{si, act, bias, sj0, W0@buf0}, G1{W1@buf1} ----
    cpblk(sb + SI,   g_s + (size_t)(i * 8192 + b0) * S_S, TB * S_S, tid);
    cpblk(sb + ACT,  g_a + (size_t)(i * 8192 + b0) * S_A, TB * S_A, tid);
    cpblk(sb + BIAS, b_edge + (size_t)(i * 9) * 128, 4608, tid);
    {
        int j0 = (i == 0) ? 1 : 0;
        cpblk(sb + SJ,  g_s + (size_t)(j0 * 8192 + b0) * S_S, TB * S_S, tid);
        cpblk(sb + WE0, g_We + (size_t)(i * 9) * (128 * S_W), 128 * S_W, tid);
    }
    CP_COMMIT();
    cpblk(sb + WE1, g_We + (size_t)(i * 9 + 1) * (128 * S_W), 128 * S_W, tid);
    CP_COMMIT();

    // lane bases (loop-invariant)
    const uint32_t aSI0 = baseA(sb + SI, m0,      S_S, lane);
    const uint32_t aSI1 = baseA(sb + SI, m0 + 16, S_S, lane);
    const uint32_t aSJ0 = baseA(sb + SJ, m0,      S_S, lane);
    const uint32_t aSJ1 = baseA(sb + SJ, m0 + 16, S_S, lane);
    uint32_t bW0[4], bW1[4];
    #pragma unroll
    for (int q = 0; q < 4; ++q) {
        bW0[q] = baseB(sb + WE0, 64 * wn + 16 * q, S_W, lane);
        bW1[q] = baseB(sb + WE1, 64 * wn + 16 * q, S_W, lane);
    }

    float C[64], agg[64];
    #pragma unroll
    for (int q = 0; q < 64; ++q) agg[q] = 0.0f;

    // ---- edge loop (W double-buffered, 2-edge lookahead) ----
    #pragma unroll
    for (int t = 0; t < 9; ++t) {
        CP_WAIT(1);          // W_t (issued t-2) + sj_t (issued t-1) complete
        __syncthreads();

        // init C from bias: cols h = 64*wn + 16q + 8hf + 2*(lane&3)
        {
            const float* bs = (const float*)(smem + BIAS) + t * 128;
            #pragma unroll
            for (int q = 0; q < 4; ++q)
                #pragma unroll
                for (int hf = 0; hf < 2; ++hf) {
                    int h = 64 * wn + 16 * q + 8 * hf + (lane & 3) * 2;
                    float2 bv = *(const float2*)&bs[h];
                    #pragma unroll
                    for (int m = 0; m < 2; ++m) {
                        float* c = C + m * 32 + q * 8 + hf * 4;
                        c[0] = bv.x; c[1] = bv.y; c[2] = bv.x; c[3] = bv.y;
                    }
                }
        }

        const uint32_t* bW = (t & 1) ? bW1 : bW0;

        #pragma unroll
        for (int ks = 0; ks < 16; ++ks) {
            const uint32_t koff = (uint32_t)((ks & 7) * 32);
            uint32_t a0[4], a1[4], b[4][4];
            if (ks < 8) {
                ldsm4(aSI0 + koff, a0);
                ldsm4(aSI1 + koff, a1);
            } else {
                ldsm4(aSJ0 + koff, a0);
                ldsm4(aSJ1 + koff, a1);
            }
            #pragma unroll
            for (int q = 0; q < 4; ++q)
                ldsm4(bW[q] + (uint32_t)(ks * 32), b[q]);
            #pragma unroll
            for (int q = 0; q < 4; ++q) {
                mma8(C + q * 8,          a0, b[q][0], b[q][1]);
                mma8(C + q * 8 + 4,      a0, b[q][2], b[q][3]);
                mma8(C + 32 + q * 8,     a1, b[q][0], b[q][1]);
                mma8(C + 32 + q * 8 + 4, a1, b[q][2], b[q][3]);
            }
        }
        __syncthreads();   // sj_t + W_t buffer fully consumed

        // issue lookahead loads: sj_{t+1} (own group), then W_{t+2} / Wn (own group)
        if (t < 8) {
            int jn = (t + 1) + ((t + 1) >= i ? 1 : 0);
            cpblk(sb + SJ, g_s + (size_t)(jn * 8192 + b0) * S_S, TB * S_S, tid);
            CP_COMMIT();
            if (t < 7) {
                uint32_t wb = (t & 1) ? (sb + WE1) : (sb + WE0);   // buffer just freed
                cpblk(wb, g_We + (size_t)(i * 9 + t + 2) * (128 * S_W), 128 * S_W, tid);
            } else {
                // t == 7: buf1 just freed; stage BOTH node-W chunks there
                cpblk(sb + WNA, g_WnA + (size_t)i * (64 * S_WNA), 64 * S_WNA, tid);
                cpblk(sb + WNB, g_WnB + (size_t)i * (64 * S_WNB), 64 * S_WNB, tid);
            }
            CP_COMMIT();
        }

        // epilogue (overlaps in-flight cp.async)
        #pragma unroll
        for (int q = 0; q < 64; ++q) agg[q] += tanha(C[q]);
    }

    // ---- node phase: write agg as tf32 A-tile [128r][128h] into AGG (=WE0) ----
    #pragma unroll
    for (int q = 0; q < 4; ++q)
        #pragma unroll
        for (int hf = 0; hf < 2; ++hf) {
            int h = 64 * wn + 16 * q + 8 * hf + (lane & 3) * 2;
            #pragma unroll
            for (int m = 0; m < 2; ++m) {
                int idx = m * 32 + q * 8 + hf * 4;
                #pragma unroll
                for (int hh = 0; hh < 2; ++hh) {
                    int r = m0 + m * 16 + (lane >> 2) + 8 * hh;
                    uint2 w = { tf32c(agg[idx + 2 * hh]), tf32c(agg[idx + 2 * hh + 1]) };
                    *(uint2*)(smem + AGG + (uint32_t)(r * S_W) + (uint32_t)(h * 4)) = w;
                }
            }
        }
    CP_WAIT(0);          // WnA + WnB staged (issued at t==7)
    __syncthreads();     // + AGG visible

    // node lane bases
    const uint32_t aACT0 = baseA(sb + ACT, m0,      S_A, lane);
    const uint32_t aACT1 = baseA(sb + ACT, m0 + 16, S_A, lane);
    const uint32_t aAG0  = baseA(sb + AGG, m0,      S_W, lane);
    const uint32_t aAG1  = baseA(sb + AGG, m0 + 16, S_W, lane);
    uint32_t bWNA[2], bWNB[2];
    bWNA[0] = baseB(sb + WNA, 32 * wn,      S_WNA, lane);
    bWNA[1] = baseB(sb + WNA, 32 * wn + 16, S_WNA, lane);
    bWNB[0] = baseB(sb + WNB, 32 * wn,      S_WNB, lane);
    bWNB[1] = baseB(sb + WNB, 32 * wn + 16, S_WNB, lane);

    // init C2 from node bias: cols d = 32*wn + 16*q2 + 8*hf + 2*(lane&3)
    float C2[32];
    #pragma unroll
    for (int q2 = 0; q2 < 2; ++q2)
        #pragma unroll
        for (int hf = 0; hf < 2; ++hf) {
            int d = 32 * wn + 16 * q2 + 8 * hf + (lane & 3) * 2;
            float2 bn = *(const float2*)&b_node[(size_t)i * 64 + d];
            #pragma unroll
            for (int m = 0; m < 2; ++m) {
                float* c = C2 + m * 16 + q2 * 8 + hf * 4;
                c[0] = bn.x; c[1] = bn.y; c[2] = bn.x; c[3] = bn.y;
            }
        }

    // node GEMM: 26 k8-steps over F=208 (chunkA ks 0..13, chunkB ks 14..25)
    #pragma unroll
    for (int ks = 0; ks < 26; ++ks) {
        uint32_t a0[4], a1[4], bN[2][4];
        if (ks < 8) {
            ldsm4(aSI0 + (uint32_t)(ks * 32), a0);
            ldsm4(aSI1 + (uint32_t)(ks * 32), a1);
        } else if (ks < 10) {
            ldsm4(aACT0 + (uint32_t)((ks - 8) * 32), a0);
            ldsm4(aACT1 + (uint32_t)((ks - 8) * 32), a1);
        } else {
            ldsm4(aAG0 + (uint32_t)((ks - 10) * 32), a0);
            ldsm4(aAG1 + (uint32_t)((ks - 10) * 32), a1);
        }
        if (ks < 14) {
            #pragma unroll
            for (int q2 = 0; q2 < 2; ++q2)
                ldsm4(bWNA[q2] + (uint32_t)(ks * 32), bN[q2]);
        } else {
            #pragma unroll
            for (int q2 = 0; q2 < 2; ++q2)
                ldsm4(bWNB[q2] + (uint32_t)((ks - 14) * 32), bN[q2]);
        }
        #pragma unroll
        for (int q2 = 0; q2 < 2; ++q2) {
            mma8(C2 + q2 * 8,          a0, bN[q2][0], bN[q2][1]);
            mma8(C2 + q2 * 8 + 4,      a0, bN[q2][2], bN[q2][3]);
            mma8(C2 + 16 + q2 * 8,     a1, bN[q2][0], bN[q2][1]);
            mma8(C2 + 16 + q2 * 8 + 4, a1, bN[q2][2], bN[q2][3]);
        }
    }

    // ---- final epilogue: tanh + store ----
    #pragma unroll
    for (int q2 = 0; q2 < 2; ++q2)
        #pragma unroll
        for (int hf = 0; hf < 2; ++hf) {
            int d = 32 * wn + 16 * q2 + 8 * hf + (lane & 3) * 2;
            #pragma unroll
            for (int m = 0; m < 2; ++m) {
                int r0 = m0 + m * 16 + (lane >> 2);
                const float* c = C2 + m * 16 + q2 * 8 + hf * 4;
                float2 v0 = { tanha(c[0]), tanha(c[1]) };
                float2 v1 = { tanha(c[2]), tanha(c[3]) };
                *(float2*)&out[((size_t)(b0 + r0)     * KN + i) * 64 + d] = v0;
                *(float2*)&out[((size_t)(b0 + r0 + 8) * KN + i) * 64 + d] = v1;
            }
        }
}

extern "C" void kernel_launch(void* const* d_in, const int* in_sizes, int n_in,
                              void* d_out, int out_size)
{
    const float* states = (const float*)d_in[0];
    const float* action = (const float*)d_in[1];
    const float* W_edge = (const float*)d_in[2];
    const float* b_edge = (const float*)d_in[3];
    const float* W_node = (const float*)d_in[4];
    const float* b_node = (const float*)d_in[5];
    float* out = (float*)d_out;

    int B = in_sizes[0] / (KN * 64);   // 8192

    prep_kernel<<<2048, 256>>>(states, action, W_edge, W_node);

    cudaFuncSetAttribute(gnn_tf32_kernel,
                         cudaFuncAttributeMaxDynamicSharedMemorySize, SMEM_TOTAL);
    dim3 grid(B / TB, KN);
    gnn_tf32_kernel<<<grid, NT, SMEM_TOTAL>>>(b_edge, b_node, out);
}

// round 16
// speedup vs baseline: 1.1543x; 1.1543x over previous
#include <cuda_runtime.h>
#include <cstdint>

// TransitionGNN via legacy mma.sync.m16n8k8 TF32 (single pass).
// R16: R13 (4-warp CTA, 2m x 2n, M32xN64, 2 CTAs/SM) + DE-PHASED edge order:
// odd CTAs traverse edges rotated by 4, so the two co-resident CTAs' load/
// barrier windows interleave with each other's MMA windows instead of
// coinciding (edge aggregation is order-invariant).
// B=8192, K=10, D=64, H=128, A=16, E=90, F=208.

#define KN 10
#define TB 64
#define NT 128

// padded row strides (bytes); (stride/4) mod 32 in {4,20} -> ldmatrix conflict-free
#define S_S   272   // states rows: 256B + 16
#define S_A   80    // action rows: 64B + 16
#define S_W   528   // W^T rows: 512B + 16
#define S_WNA 464   // Wn^T chunkA rows: 448B + 16
#define S_WNB 400   // Wn^T chunkB rows: 384B + 16

// ---- staged scratch (tf32, pre-padded rows) ----
__device__ __align__(16) unsigned char g_s[KN * 8192 * S_S];      // [j][b][64k]
__device__ __align__(16) unsigned char g_a[KN * 8192 * S_A];      // [j][b][16a]
__device__ __align__(16) unsigned char g_We[90 * 128 * S_W];      // W^T [e][128h][128k]
__device__ __align__(16) unsigned char g_WnA[KN * 64 * S_WNA];    // Wn^T [i][64d][f0..111]
__device__ __align__(16) unsigned char g_WnB[KN * 64 * S_WNB];    // Wn^T [i][64d][f112..207]

// ---- smem map (bytes), per CTA 112128 => 2 CTAs/SM ----
#define SI    0u                    // 64 x 272 = 17408
#define SJ    17408u                // 17408
#define ACT   34816u                // 64 x 80 = 5120
#define BIAS  39936u                // 4608 (9 x 512)
#define WE    44544u                // 128 x 528 = 67584
#define SMEM_TOTAL 112128
// node-phase aliases inside WE:
#define AGG   (WE)                  // 64 x 528 = 33792
#define WN    (WE + 33792u)         // <= 29696

__device__ __forceinline__ uint32_t tf32c(float x) {
    uint32_t r; asm("cvt.rna.tf32.f32 %0, %1;" : "=r"(r) : "f"(x)); return r;
}
__device__ __forceinline__ float tanha(float x) {
    float r; asm("tanh.approx.f32 %0, %1;" : "=f"(r) : "f"(x)); return r;
}
__device__ __forceinline__ void cp16(uint32_t s, const void* g) {
    asm volatile("cp.async.cg.shared.global [%0], [%1], 16;" :: "r"(s), "l"(g));
}
__device__ __forceinline__ void cpblk(uint32_t sdst, const void* gsrc, int bytes, int tid) {
    for (int off = tid * 16; off < bytes; off += NT * 16)
        cp16(sdst + off, (const char*)gsrc + off);
}
#define CP_COMMIT() asm volatile("cp.async.commit_group;")
#define CP_WAIT0()  asm volatile("cp.async.wait_group 0;")

__device__ __forceinline__ void ldsm4(uint32_t a, uint32_t r[4]) {
    asm volatile("ldmatrix.sync.aligned.m8n8.x4.shared.b16 {%0,%1,%2,%3}, [%4];"
        : "=r"(r[0]), "=r"(r[1]), "=r"(r[2]), "=r"(r[3]) : "r"(a));
}
__device__ __forceinline__ void mma8(float c[4], const uint32_t a[4], uint32_t b0, uint32_t b1) {
    asm volatile("mma.sync.aligned.m16n8k8.row.col.f32.tf32.tf32.f32 "
        "{%0,%1,%2,%3},{%4,%5,%6,%7},{%8,%9},{%0,%1,%2,%3};"
        : "+f"(c[0]), "+f"(c[1]), "+f"(c[2]), "+f"(c[3])
        : "r"(a[0]), "r"(a[1]), "r"(a[2]), "r"(a[3]), "r"(b0), "r"(b1));
}
// A-tile lane base (m16 x k8 x4-ldmatrix); addr(ks) = base + ks*32
__device__ __forceinline__ uint32_t baseA(uint32_t buf, int r0, int S, int lane) {
    int row = r0 + (lane & 7) + ((lane >> 3) & 1) * 8;
    return buf + (uint32_t)(row * S) + ((uint32_t)(lane >> 4) << 4);
}
// B-tile lane base (n16 x k8 x4-ldmatrix from W^T rows=n); addr(ks) = base + ks*32
__device__ __forceinline__ uint32_t baseB(uint32_t buf, int r0, int S, int lane) {
    int row = r0 + (lane & 7) + ((lane >> 4) << 3);
    return buf + (uint32_t)(row * S) + ((uint32_t)((lane >> 3) & 1) << 4);
}

// ===================== prep kernel =====================
__global__ void prep_kernel(const float* __restrict__ states, const float* __restrict__ action,
                            const float* __restrict__ Wed, const float* __restrict__ Wn)
{
    int tid = blockIdx.x * blockDim.x + threadIdx.x;
    int NTH = gridDim.x * blockDim.x;
    for (int p = tid; p < KN * 8192 * 32; p += NTH) {
        int d2 = p & 31, b = (p >> 5) & 8191, j = p >> 18;
        float2 v = *(const float2*)&states[((size_t)b * KN + j) * 64 + 2 * d2];
        uint2 w = { tf32c(v.x), tf32c(v.y) };
        *(uint2*)(g_s + (size_t)(j * 8192 + b) * S_S + d2 * 8) = w;
    }
    for (int p = tid; p < KN * 8192 * 8; p += NTH) {
        int a2 = p & 7, b = (p >> 3) & 8191, j = p >> 16;
        float2 v = *(const float2*)&action[((size_t)b * KN + j) * 16 + 2 * a2];
        uint2 w = { tf32c(v.x), tf32c(v.y) };
        *(uint2*)(g_a + (size_t)(j * 8192 + b) * S_A + a2 * 8) = w;
    }
    for (int p = tid; p < 90 * 128 * 64; p += NTH) {
        int h2 = p & 63, k = (p >> 6) & 127, e = p >> 13;
        float2 v = *(const float2*)&Wed[((size_t)e * 128 + k) * 128 + 2 * h2];
        int h0 = 2 * h2;
        *(uint32_t*)(g_We + (size_t)(e * 128 + h0)     * S_W + k * 4) = tf32c(v.x);
        *(uint32_t*)(g_We + (size_t)(e * 128 + h0 + 1) * S_W + k * 4) = tf32c(v.y);
    }
    for (int p = tid; p < KN * 208 * 32; p += NTH) {
        int d2 = p & 31, fi = p >> 5;
        int f = fi % 208, i = fi / 208;
        float2 v = *(const float2*)&Wn[((size_t)i * 208 + f) * 64 + 2 * d2];
        int d0 = 2 * d2;
        if (f < 112) {
            unsigned char* base = g_WnA + (size_t)i * (64 * S_WNA);
            *(uint32_t*)(base + (size_t)d0       * S_WNA + f * 4) = tf32c(v.x);
            *(uint32_t*)(base + (size_t)(d0 + 1) * S_WNA + f * 4) = tf32c(v.y);
        } else {
            unsigned char* base = g_WnB + (size_t)i * (64 * S_WNB);
            int fc = f - 112;
            *(uint32_t*)(base + (size_t)d0       * S_WNB + fc * 4) = tf32c(v.x);
            *(uint32_t*)(base + (size_t)(d0 + 1) * S_WNB + fc * 4) = tf32c(v.y);
        }
    }
}

// ===================== main kernel =====================
extern "C" __global__ void __launch_bounds__(NT, 2)
gnn_tf32_kernel(const float* __restrict__ b_edge,   // [E,H]
                const float* __restrict__ b_node,   // [K,D]
                float* __restrict__ out)            // [B,K,D]
{
    extern __shared__ char smem[];
    const uint32_t sb = (uint32_t)__cvta_generic_to_shared(smem);

    const int i    = blockIdx.y;
    const int b0   = blockIdx.x * TB;
    const int tid  = threadIdx.x;
    const int lane = tid & 31;
    const int wid  = tid >> 5;
    const int wm   = wid & 1;    // 2 m-warps: rows 32*wm .. +31
    const int wn   = wid >> 1;   // 2 n-warps: edge cols 64*wn, node cols 32*wn
    const int m0   = 32 * wm;

    // de-phase: odd CTAs traverse edges rotated by 4 (sum is order-invariant)
    const int ph = (blockIdx.x & 1) * 4;

    // ---- prologue: si, act, bias(all 9), sj@te0, W@te0 (one group) ----
    cpblk(sb + SI,   g_s + (size_t)(i * 8192 + b0) * S_S, TB * S_S, tid);
    cpblk(sb + ACT,  g_a + (size_t)(i * 8192 + b0) * S_A, TB * S_A, tid);
    cpblk(sb + BIAS, b_edge + (size_t)(i * 9) * 128, 4608, tid);
    {
        int te0 = ph;
        int j0  = te0 + (te0 >= i ? 1 : 0);
        cpblk(sb + SJ, g_s + (size_t)(j0 * 8192 + b0) * S_S, TB * S_S, tid);
        cpblk(sb + WE, g_We + (size_t)(i * 9 + te0) * (128 * S_W), 128 * S_W, tid);
    }
    CP_COMMIT();

    // lane bases (loop-invariant)
    const uint32_t aSI0 = baseA(sb + SI, m0,      S_S, lane);
    const uint32_t aSI1 = baseA(sb + SI, m0 + 16, S_S, lane);
    const uint32_t aSJ0 = baseA(sb + SJ, m0,      S_S, lane);
    const uint32_t aSJ1 = baseA(sb + SJ, m0 + 16, S_S, lane);
    uint32_t bWE[4];
    #pragma unroll
    for (int q = 0; q < 4; ++q)
        bWE[q] = baseB(sb + WE, 64 * wn + 16 * q, S_W, lane);

    float C[64], agg[64];
    #pragma unroll
    for (int q = 0; q < 64; ++q) agg[q] = 0.0f;

    // ---- edge loop (rotated order) ----
    #pragma unroll
    for (int t = 0; t < 9; ++t) {
        int te = t + ph; if (te >= 9) te -= 9;   // this CTA's edge slot

        CP_WAIT0();
        __syncthreads();     // W_te, sj_te (t==0: +si/act/bias) visible

        // init C from bias of edge te
        {
            const float* bs = (const float*)(smem + BIAS) + te * 128;
            #pragma unroll
            for (int q = 0; q < 4; ++q)
                #pragma unroll
                for (int hf = 0; hf < 2; ++hf) {
                    int h = 64 * wn + 16 * q + 8 * hf + (lane & 3) * 2;
                    float2 bv = *(const float2*)&bs[h];
                    #pragma unroll
                    for (int m = 0; m < 2; ++m) {
                        float* c = C + m * 32 + q * 8 + hf * 4;
                        c[0] = bv.x; c[1] = bv.y; c[2] = bv.x; c[3] = bv.y;
                    }
                }
        }

        #pragma unroll
        for (int ks = 0; ks < 16; ++ks) {
            const uint32_t koff = (uint32_t)((ks & 7) * 32);
            uint32_t a0[4], a1[4], b[4][4];
            if (ks < 8) {
                ldsm4(aSI0 + koff, a0);
                ldsm4(aSI1 + koff, a1);
            } else {
                ldsm4(aSJ0 + koff, a0);
                ldsm4(aSJ1 + koff, a1);
            }
            #pragma unroll
            for (int q = 0; q < 4; ++q)
                ldsm4(bWE[q] + (uint32_t)(ks * 32), b[q]);
            #pragma unroll
            for (int q = 0; q < 4; ++q) {
                mma8(C + q * 8,          a0, b[q][0], b[q][1]);
                mma8(C + q * 8 + 4,      a0, b[q][2], b[q][3]);
                mma8(C + 32 + q * 8,     a1, b[q][0], b[q][1]);
                mma8(C + 32 + q * 8 + 4, a1, b[q][2], b[q][3]);
            }
        }
        __syncthreads();   // W_te / sj_te fully consumed

        // issue next loads (buffers free)
        if (t < 8) {
            int ten = t + 1 + ph; if (ten >= 9) ten -= 9;
            int jn  = ten + (ten >= i ? 1 : 0);
            cpblk(sb + SJ, g_s + (size_t)(jn * 8192 + b0) * S_S, TB * S_S, tid);
            cpblk(sb + WE, g_We + (size_t)(i * 9 + ten) * (128 * S_W), 128 * S_W, tid);
        } else {
            cpblk(sb + WN, g_WnA + (size_t)i * (64 * S_WNA), 64 * S_WNA, tid);
        }
        CP_COMMIT();

        // epilogue (overlaps in-flight cp.async + other CTA's MMAs)
        #pragma unroll
        for (int q = 0; q < 64; ++q) agg[q] += tanha(C[q]);
    }

    // ---- node phase: write agg as tf32 A-tile [64r][128h], rows of 528B ----
    #pragma unroll
    for (int q = 0; q < 4; ++q)
        #pragma unroll
        for (int hf = 0; hf < 2; ++hf) {
            int h = 64 * wn + 16 * q + 8 * hf + (lane & 3) * 2;
            #pragma unroll
            for (int m = 0; m < 2; ++m) {
                int idx = m * 32 + q * 8 + hf * 4;
                #pragma unroll
                for (int hh = 0; hh < 2; ++hh) {
                    int r = m0 + m * 16 + (lane >> 2) + 8 * hh;
                    uint2 w = { tf32c(agg[idx + 2 * hh]), tf32c(agg[idx + 2 * hh + 1]) };
                    *(uint2*)(smem + AGG + (uint32_t)(r * S_W) + (uint32_t)(h * 4)) = w;
                }
            }
        }
    CP_WAIT0();          // WnA staged
    __syncthreads();     // + AGG visible

    // node lane bases
    const uint32_t aACT0 = baseA(sb + ACT, m0,      S_A, lane);
    const uint32_t aACT1 = baseA(sb + ACT, m0 + 16, S_A, lane);
    const uint32_t aAG0  = baseA(sb + AGG, m0,      S_W, lane);
    const uint32_t aAG1  = baseA(sb + AGG, m0 + 16, S_W, lane);

    // init C2 from node bias: cols d = 32*wn + 16*q2 + 8*hf + 2*(lane&3)
    float C2[32];
    #pragma unroll
    for (int q2 = 0; q2 < 2; ++q2)
        #pragma unroll
        for (int hf = 0; hf < 2; ++hf) {
            int d = 32 * wn + 16 * q2 + 8 * hf + (lane & 3) * 2;
            float2 bn = *(const float2*)&b_node[(size_t)i * 64 + d];
            #pragma unroll
            for (int m = 0; m < 2; ++m) {
                float* c = C2 + m * 16 + q2 * 8 + hf * 4;
                c[0] = bn.x; c[1] = bn.y; c[2] = bn.x; c[3] = bn.y;
            }
        }

    // node GEMM: 26 k8-steps over F=208; WN chunkA = ks 0..13, chunkB = ks 14..25
    #pragma unroll
    for (int chunk = 0; chunk < 2; ++chunk) {
        const int S_WN = chunk ? S_WNB : S_WNA;
        uint32_t bWN[2];
        bWN[0] = baseB(sb + WN, 32 * wn,      S_WN, lane);
        bWN[1] = baseB(sb + WN, 32 * wn + 16, S_WN, lane);
        const int ksBeg = chunk ? 14 : 0;
        const int ksEnd = chunk ? 26 : 14;
        #pragma unroll
        for (int ks = ksBeg; ks < ksEnd; ++ks) {
            uint32_t a0[4], a1[4], bN[2][4];
            if (ks < 8) {
                ldsm4(aSI0 + (uint32_t)(ks * 32), a0);
                ldsm4(aSI1 + (uint32_t)(ks * 32), a1);
            } else if (ks < 10) {
                ldsm4(aACT0 + (uint32_t)((ks - 8) * 32), a0);
                ldsm4(aACT1 + (uint32_t)((ks - 8) * 32), a1);
            } else {
                ldsm4(aAG0 + (uint32_t)((ks - 10) * 32), a0);
                ldsm4(aAG1 + (uint32_t)((ks - 10) * 32), a1);
            }
            #pragma unroll
            for (int q2 = 0; q2 < 2; ++q2)
                ldsm4(bWN[q2] + (uint32_t)((ks - ksBeg) * 32), bN[q2]);
            #pragma unroll
            for (int q2 = 0; q2 < 2; ++q2) {
                mma8(C2 + q2 * 8,          a0, bN[q2][0], bN[q2][1]);
                mma8(C2 + q2 * 8 + 4,      a0, bN[q2][2], bN[q2][3]);
                mma8(C2 + 16 + q2 * 8,     a1, bN[q2][0], bN[q2][1]);
                mma8(C2 + 16 + q2 * 8 + 4, a1, bN[q2][2], bN[q2][3]);
            }
        }
        if (chunk == 0) {
            __syncthreads();   // WnA fully consumed
            cpblk(sb + WN, g_WnB + (size_t)i * (64 * S_WNB), 64 * S_WNB, tid);
            CP_COMMIT();
            CP_WAIT0();
            __syncthreads();   // WnB staged
        }
    }

    // ---- final epilogue: tanh + store ----
    #pragma unroll
    for (int q2 = 0; q2 < 2; ++q2)
        #pragma unroll
        for (int hf = 0; hf < 2; ++hf) {
            int d = 32 * wn + 16 * q2 + 8 * hf + (lane & 3) * 2;
            #pragma unroll
            for (int m = 0; m < 2; ++m) {
                int r0 = m0 + m * 16 + (lane >> 2);
                const float* c = C2 + m * 16 + q2 * 8 + hf * 4;
                float2 v0 = { tanha(c[0]), tanha(c[1]) };
                float2 v1 = { tanha(c[2]), tanha(c[3]) };
                *(float2*)&out[((size_t)(b0 + r0)     * KN + i) * 64 + d] = v0;
                *(float2*)&out[((size_t)(b0 + r0 + 8) * KN + i) * 64 + d] = v1;
            }
        }
}

extern "C" void kernel_launch(void* const* d_in, const int* in_sizes, int n_in,
                              void* d_out, int out_size)
{
    const float* states = (const float*)d_in[0];
    const float* action = (const float*)d_in[1];
    const float* W_edge = (const float*)d_in[2];
    const float* b_edge = (const float*)d_in[3];
    const float* W_node = (const float*)d_in[4];
    const float* b_node = (const float*)d_in[5];
    float* out = (float*)d_out;

    int B = in_sizes[0] / (KN * 64);   // 8192

    prep_kernel<<<2048, 256>>>(states, action, W_edge, W_node);

    cudaFuncSetAttribute(gnn_tf32_kernel,
                         cudaFuncAttributeMaxDynamicSharedMemorySize, SMEM_TOTAL);
    dim3 grid(B / TB, KN);
    gnn_tf32_kernel<<<grid, NT, SMEM_TOTAL>>>(b_edge, b_node, out);
}

// round 17
// speedup vs baseline: 1.8281x; 1.5837x over previous
#include <cuda_runtime.h>
#include <cstdint>

// TransitionGNN via legacy mma.sync.m16n8k16 FP16 (f32 accumulate), single pass.
// R17: fp16 == tf32 in significand bits (11) => same ~4.9e-4 rel_err, but HALF
// the tensor instructions and HALF the ldsm/L2 bytes. R13 tiles (4-warp CTA,
// 2m x 2n, M32xN64), 2 CTAs/SM, R16 de-phased edge order.
// B=8192, K=10, D=64, H=128, A=16, E=90, F=208.

#define KN 10
#define TB 64
#define NT 128

// padded row strides (bytes); (stride words) mod 32 in {4,12,20,28} -> ldmatrix conflict-free
#define S_S   144   // states rows: 64 fp16 = 128B + 16   (36 w, mod32=4)
#define S_A   48    // action rows: 16 fp16 = 32B + 16    (12 w, mod32=12)
#define S_W   272   // W rows (k): 128 fp16 = 256B + 16   (68 w, mod32=4)
#define S_AG  272   // agg rows: 128 fp16 = 256B + 16
#define S_WN  144   // Wn rows (f): 64 fp16 = 128B + 16

// ---- staged scratch (fp16, pre-padded rows) ----
__device__ __align__(16) unsigned char g_s[KN * 8192 * S_S];      // [j][b][64d]
__device__ __align__(16) unsigned char g_a[KN * 8192 * S_A];      // [j][b][16a]
__device__ __align__(16) unsigned char g_We[90 * 128 * S_W];      // [e][128k][128h]
__device__ __align__(16) unsigned char g_Wn[KN * 208 * S_WN];     // [i][208f][64d]

// ---- smem map (bytes), per CTA 73472 => 2 CTAs/SM ----
#define SI    0u                    // 64 x 144 = 9216
#define SJ    9216u                 // 9216
#define ACT   18432u                // 64 x 48 = 3072
#define BIAS  21504u                // 4608 (9 x 512, f32)
#define WE    26112u                // 128 x 272 = 34816
#define SMEM_TOTAL 73472
// node-phase aliases:
#define AGG   (WE)                  // 64 x 272 = 17408
#define WN    (WE + 17408u)         // 208 x 144 = 29952

__device__ __forceinline__ uint32_t f16x2(float lo, float hi) {
    uint32_t r; asm("cvt.rn.f16x2.f32 %0, %1, %2;" : "=r"(r) : "f"(hi), "f"(lo)); return r;
}
__device__ __forceinline__ float tanha(float x) {
    float r; asm("tanh.approx.f32 %0, %1;" : "=f"(r) : "f"(x)); return r;
}
__device__ __forceinline__ void cp16(uint32_t s, const void* g) {
    asm volatile("cp.async.cg.shared.global [%0], [%1], 16;" :: "r"(s), "l"(g));
}
__device__ __forceinline__ void cpblk(uint32_t sdst, const void* gsrc, int bytes, int tid) {
    for (int off = tid * 16; off < bytes; off += NT * 16)
        cp16(sdst + off, (const char*)gsrc + off);
}
#define CP_COMMIT() asm volatile("cp.async.commit_group;")
#define CP_WAIT0()  asm volatile("cp.async.wait_group 0;")

__device__ __forceinline__ void ldsm4(uint32_t a, uint32_t r[4]) {
    asm volatile("ldmatrix.sync.aligned.m8n8.x4.shared.b16 {%0,%1,%2,%3}, [%4];"
        : "=r"(r[0]), "=r"(r[1]), "=r"(r[2]), "=r"(r[3]) : "r"(a));
}
__device__ __forceinline__ void ldsm4t(uint32_t a, uint32_t r[4]) {
    asm volatile("ldmatrix.sync.aligned.m8n8.x4.trans.shared.b16 {%0,%1,%2,%3}, [%4];"
        : "=r"(r[0]), "=r"(r[1]), "=r"(r[2]), "=r"(r[3]) : "r"(a));
}
__device__ __forceinline__ void mma16(float c[4], const uint32_t a[4], uint32_t b0, uint32_t b1) {
    asm volatile("mma.sync.aligned.m16n8k16.row.col.f32.f16.f16.f32 "
        "{%0,%1,%2,%3},{%4,%5,%6,%7},{%8,%9},{%0,%1,%2,%3};"
        : "+f"(c[0]), "+f"(c[1]), "+f"(c[2]), "+f"(c[3])
        : "r"(a[0]), "r"(a[1]), "r"(a[2]), "r"(a[3]), "r"(b0), "r"(b1));
}
// A-tile lane base (m16 x k16 x4-ldmatrix, rows=batch); addr(ks) = base + ks*32
__device__ __forceinline__ uint32_t baseA(uint32_t buf, int r0, int S, int lane) {
    int row = r0 + (lane & 7) + ((lane >> 3) & 1) * 8;
    return buf + (uint32_t)(row * S) + ((uint32_t)(lane >> 4) << 4);
}
// B-tile lane base (k16 x n16 via trans-ldsm4 on rows=k tile); addr(ks) = base + ks*16*S
__device__ __forceinline__ uint32_t baseBt(uint32_t buf, int c0, int S, int lane) {
    int row = lane & 15;
    int chunk = c0 + (lane >> 4);
    return buf + (uint32_t)(row * S) + ((uint32_t)chunk << 4);
}

// ===================== prep kernel =====================
__global__ void prep_kernel(const float* __restrict__ states, const float* __restrict__ action,
                            const float* __restrict__ Wed, const float* __restrict__ Wn)
{
    int tid = blockIdx.x * blockDim.x + threadIdx.x;
    int NTH = gridDim.x * blockDim.x;
    // states: rows (j,b), 64 d fp16
    for (int p = tid; p < KN * 8192 * 32; p += NTH) {
        int d2 = p & 31, b = (p >> 5) & 8191, j = p >> 18;
        float2 v = *(const float2*)&states[((size_t)b * KN + j) * 64 + 2 * d2];
        *(uint32_t*)(g_s + (size_t)(j * 8192 + b) * S_S + d2 * 4) = f16x2(v.x, v.y);
    }
    // action: rows (j,b), 16 a fp16
    for (int p = tid; p < KN * 8192 * 8; p += NTH) {
        int a2 = p & 7, b = (p >> 3) & 8191, j = p >> 16;
        float2 v = *(const float2*)&action[((size_t)b * KN + j) * 16 + 2 * a2];
        *(uint32_t*)(g_a + (size_t)(j * 8192 + b) * S_A + a2 * 4) = f16x2(v.x, v.y);
    }
    // W_edge [e][k][h]: rows k, 128 h fp16 (coalesced reads over h)
    for (int p = tid; p < 90 * 128 * 64; p += NTH) {
        int h2 = p & 63, k = (p >> 6) & 127, e = p >> 13;
        float2 v = *(const float2*)&Wed[((size_t)e * 128 + k) * 128 + 2 * h2];
        *(uint32_t*)(g_We + (size_t)(e * 128 + k) * S_W + h2 * 4) = f16x2(v.x, v.y);
    }
    // W_node [i][f][d]: rows f, 64 d fp16
    for (int p = tid; p < KN * 208 * 32; p += NTH) {
        int d2 = p & 31, fi = p >> 5;
        int f = fi % 208, i = fi / 208;
        float2 v = *(const float2*)&Wn[((size_t)i * 208 + f) * 64 + 2 * d2];
        *(uint32_t*)(g_Wn + (size_t)(i * 208 + f) * S_WN + d2 * 4) = f16x2(v.x, v.y);
    }
}

// ===================== main kernel =====================
extern "C" __global__ void __launch_bounds__(NT, 2)
gnn_f16_kernel(const float* __restrict__ b_edge,   // [E,H]
               const float* __restrict__ b_node,   // [K,D]
               float* __restrict__ out)            // [B,K,D]
{
    extern __shared__ char smem[];
    const uint32_t sb = (uint32_t)__cvta_generic_to_shared(smem);

    const int i    = blockIdx.y;
    const int b0   = blockIdx.x * TB;
    const int tid  = threadIdx.x;
    const int lane = tid & 31;
    const int wid  = tid >> 5;
    const int wm   = wid & 1;    // 2 m-warps: rows 32*wm .. +31
    const int wn   = wid >> 1;   // 2 n-warps: edge cols 64*wn, node cols 32*wn
    const int m0   = 32 * wm;

    // de-phase: odd CTAs traverse edges rotated by 4 (order-invariant sum)
    const int ph = (blockIdx.x & 1) * 4;

    // ---- prologue: si, act, bias(all 9), sj@te0, W@te0 ----
    cpblk(sb + SI,   g_s + (size_t)(i * 8192 + b0) * S_S, TB * S_S, tid);
    cpblk(sb + ACT,  g_a + (size_t)(i * 8192 + b0) * S_A, TB * S_A, tid);
    cpblk(sb + BIAS, b_edge + (size_t)(i * 9) * 128, 4608, tid);
    {
        int te0 = ph;
        int j0  = te0 + (te0 >= i ? 1 : 0);
        cpblk(sb + SJ, g_s + (size_t)(j0 * 8192 + b0) * S_S, TB * S_S, tid);
        cpblk(sb + WE, g_We + (size_t)(i * 9 + te0) * (128 * S_W), 128 * S_W, tid);
    }
    CP_COMMIT();

    // lane bases (loop-invariant)
    const uint32_t aSI0 = baseA(sb + SI, m0,      S_S, lane);
    const uint32_t aSI1 = baseA(sb + SI, m0 + 16, S_S, lane);
    const uint32_t aSJ0 = baseA(sb + SJ, m0,      S_S, lane);
    const uint32_t aSJ1 = baseA(sb + SJ, m0 + 16, S_S, lane);
    uint32_t bWE[4];
    #pragma unroll
    for (int q = 0; q < 4; ++q)           // n-chunk base: cols 64*wn + 16q -> chunk 8*wn + 2q
        bWE[q] = baseBt(sb + WE, 8 * wn + 2 * q, S_W, lane);

    float C[64], agg[64];
    #pragma unroll
    for (int q = 0; q < 64; ++q) agg[q] = 0.0f;

    // ---- edge loop (rotated order; 8 k16-steps per edge) ----
    #pragma unroll
    for (int t = 0; t < 9; ++t) {
        int te = t + ph; if (te >= 9) te -= 9;

        CP_WAIT0();
        __syncthreads();     // W_te, sj_te (t==0: +si/act/bias) visible

        // init C from bias of edge te
        {
            const float* bs = (const float*)(smem + BIAS) + te * 128;
            #pragma unroll
            for (int q = 0; q < 4; ++q)
                #pragma unroll
                for (int hf = 0; hf < 2; ++hf) {
                    int h = 64 * wn + 16 * q + 8 * hf + (lane & 3) * 2;
                    float2 bv = *(const float2*)&bs[h];
                    #pragma unroll
                    for (int m = 0; m < 2; ++m) {
                        float* c = C + m * 32 + q * 8 + hf * 4;
                        c[0] = bv.x; c[1] = bv.y; c[2] = bv.x; c[3] = bv.y;
                    }
                }
        }

        #pragma unroll
        for (int ks = 0; ks < 8; ++ks) {       // k16 steps over K=128 concat dim
            const uint32_t koffA = (uint32_t)((ks & 3) * 32);
            uint32_t a0[4], a1[4], b[4][4];
            if (ks < 4) {
                ldsm4(aSI0 + koffA, a0);
                ldsm4(aSI1 + koffA, a1);
            } else {
                ldsm4(aSJ0 + koffA, a0);
                ldsm4(aSJ1 + koffA, a1);
            }
            const uint32_t koffB = (uint32_t)(ks * 16 * S_W);
            #pragma unroll
            for (int q = 0; q < 4; ++q)
                ldsm4t(bWE[q] + koffB, b[q]);
            #pragma unroll
            for (int q = 0; q < 4; ++q) {
                mma16(C + q * 8,          a0, b[q][0], b[q][1]);
                mma16(C + q * 8 + 4,      a0, b[q][2], b[q][3]);
                mma16(C + 32 + q * 8,     a1, b[q][0], b[q][1]);
                mma16(C + 32 + q * 8 + 4, a1, b[q][2], b[q][3]);
            }
        }
        __syncthreads();   // W_te / sj_te fully consumed

        // issue next loads (buffers free)
        if (t < 8) {
            int ten = t + 1 + ph; if (ten >= 9) ten -= 9;
            int jn  = ten + (ten >= i ? 1 : 0);
            cpblk(sb + SJ, g_s + (size_t)(jn * 8192 + b0) * S_S, TB * S_S, tid);
            cpblk(sb + WE, g_We + (size_t)(i * 9 + ten) * (128 * S_W), 128 * S_W, tid);
        } else {
            cpblk(sb + WN, g_Wn + (size_t)i * (208 * S_WN), 208 * S_WN, tid);
        }
        CP_COMMIT();

        // epilogue (overlaps in-flight cp.async + other CTA's MMAs)
        #pragma unroll
        for (int q = 0; q < 64; ++q) agg[q] += tanha(C[q]);
    }

    // ---- node phase: write agg as fp16 A-tile [64r][128h] into AGG ----
    #pragma unroll
    for (int q = 0; q < 4; ++q)
        #pragma unroll
        for (int hf = 0; hf < 2; ++hf) {
            int h = 64 * wn + 16 * q + 8 * hf + (lane & 3) * 2;
            #pragma unroll
            for (int m = 0; m < 2; ++m) {
                int idx = m * 32 + q * 8 + hf * 4;
                #pragma unroll
                for (int hh = 0; hh < 2; ++hh) {
                    int r = m0 + m * 16 + (lane >> 2) + 8 * hh;
                    *(uint32_t*)(smem + AGG + (uint32_t)(r * S_AG) + (uint32_t)(h * 2)) =
                        f16x2(agg[idx + 2 * hh], agg[idx + 2 * hh + 1]);
                }
            }
        }
    CP_WAIT0();          // Wn staged
    __syncthreads();     // + AGG visible

    // node lane bases
    const uint32_t aACT0 = baseA(sb + ACT, m0,      S_A, lane);
    const uint32_t aACT1 = baseA(sb + ACT, m0 + 16, S_A, lane);
    const uint32_t aAG0  = baseA(sb + AGG, m0,      S_AG, lane);
    const uint32_t aAG1  = baseA(sb + AGG, m0 + 16, S_AG, lane);
    uint32_t bWN[2];
    bWN[0] = baseBt(sb + WN, 4 * wn,     S_WN, lane);   // node cols 32*wn
    bWN[1] = baseBt(sb + WN, 4 * wn + 2, S_WN, lane);   // + 16

    // init C2 from node bias
    float C2[32];
    #pragma unroll
    for (int q2 = 0; q2 < 2; ++q2)
        #pragma unroll
        for (int hf = 0; hf < 2; ++hf) {
            int d = 32 * wn + 16 * q2 + 8 * hf + (lane & 3) * 2;
            float2 bn = *(const float2*)&b_node[(size_t)i * 64 + d];
            #pragma unroll
            for (int m = 0; m < 2; ++m) {
                float* c = C2 + m * 16 + q2 * 8 + hf * 4;
                c[0] = bn.x; c[1] = bn.y; c[2] = bn.x; c[3] = bn.y;
            }
        }

    // node GEMM: 13 k16-steps over F=208 (si 0..3, act 4, agg 5..12)
    #pragma unroll
    for (int ks = 0; ks < 13; ++ks) {
        uint32_t a0[4], a1[4], bN[2][4];
        if (ks < 4) {
            ldsm4(aSI0 + (uint32_t)(ks * 32), a0);
            ldsm4(aSI1 + (uint32_t)(ks * 32), a1);
        } else if (ks == 4) {
            ldsm4(aACT0, a0);
            ldsm4(aACT1, a1);
        } else {
            ldsm4(aAG0 + (uint32_t)((ks - 5) * 32), a0);
            ldsm4(aAG1 + (uint32_t)((ks - 5) * 32), a1);
        }
        const uint32_t koffB = (uint32_t)(ks * 16 * S_WN);
        #pragma unroll
        for (int q2 = 0; q2 < 2; ++q2)
            ldsm4t(bWN[q2] + koffB, bN[q2]);
        #pragma unroll
        for (int q2 = 0; q2 < 2; ++q2) {
            mma16(C2 + q2 * 8,          a0, bN[q2][0], bN[q2][1]);
            mma16(C2 + q2 * 8 + 4,      a0, bN[q2][2], bN[q2][3]);
            mma16(C2 + 16 + q2 * 8,     a1, bN[q2][0], bN[q2][1]);
            mma16(C2 + 16 + q2 * 8 + 4, a1, bN[q2][2], bN[q2][3]);
        }
    }

    // ---- final epilogue: tanh + store ----
    #pragma unroll
    for (int q2 = 0; q2 < 2; ++q2)
        #pragma unroll
        for (int hf = 0; hf < 2; ++hf) {
            int d = 32 * wn + 16 * q2 + 8 * hf + (lane & 3) * 2;
            #pragma unroll
            for (int m = 0; m < 2; ++m) {
                int r0 = m0 + m * 16 + (lane >> 2);
                const float* c = C2 + m * 16 + q2 * 8 + hf * 4;
                float2 v0 = { tanha(c[0]), tanha(c[1]) };
                float2 v1 = { tanha(c[2]), tanha(c[3]) };
                *(float2*)&out[((size_t)(b0 + r0)     * KN + i) * 64 + d] = v0;
                *(float2*)&out[((size_t)(b0 + r0 + 8) * KN + i) * 64 + d] = v1;
            }
        }
}

extern "C" void kernel_launch(void* const* d_in, const int* in_sizes, int n_in,
                              void* d_out, int out_size)
{
    const float* states = (const float*)d_in[0];
    const float* action = (const float*)d_in[1];
    const float* W_edge = (const float*)d_in[2];
    const float* b_edge = (const float*)d_in[3];
    const float* W_node = (const float*)d_in[4];
    const float* b_node = (const float*)d_in[5];
    float* out = (float*)d_out;

    int B = in_sizes[0] / (KN * 64);   // 8192

    prep_kernel<<<2048, 256>>>(states, action, W_edge, W_node);

    cudaFuncSetAttribute(gnn_f16_kernel,
                         cudaFuncAttributeMaxDynamicSharedMemorySize, SMEM_TOTAL);
    dim3 grid(B / TB, KN);
    gnn_f16_kernel<<<grid, NT, SMEM_TOTAL>>>(b_edge, b_node, out);
}